// round 13
// baseline (speedup 1.0000x reference)
#include <cuda_runtime.h>
#include <cuda_bf16.h>
#include <stdint.h>

#define SQ 512
#define DD 256

// ------------------- device scratch -------------------
__device__ float g_Kp[SQ*DD];                      // k = key + key@Wk + bk
__device__ float g_Vp[SQ*DD];                      // v = value + value@Wva + bva
__device__ float g_A [DD*DD];                      // A[d][e] = Wl[d][e] + (d==e)
__device__ float g_vs[SQ*DD];                      // value_sum accumulator
// q hi/lo bf16: 16 k-chunks of 16k; chunk = 512 rows x 32B, U32 swizzle
__device__ __align__(16) uint8_t g_Qhi[SQ*DD*2];
__device__ __align__(16) uint8_t g_Qlo[SQ*DD*2];

// 64B-row swizzle (B tiles): 16B unit p at row r -> unit p ^ ((r>>1)&3)
#define U64SWZ(r, p) ((uint32_t)((r) * 64 + ((((p) ^ (((r) >> 1) & 3))) << 4)))
// 32B-row swizzle (Q chunks): 16B unit p at row r -> unit p ^ ((r>>2)&1)
#define U32SWZ(r, p) ((uint32_t)((r) * 32 + ((((p) ^ (((r) >> 2) & 1))) << 4)))

// ------------------- helpers -------------------
__device__ __forceinline__ uint32_t smem_u32(const void* p) {
    uint32_t a;
    asm("{ .reg .u64 t; cvta.to.shared.u64 t, %1; cvt.u32.u64 %0, t; }" : "=r"(a) : "l"(p));
    return a;
}
__device__ __forceinline__ void ldsm_x4(uint32_t* r, uint32_t a) {
    asm volatile("ldmatrix.sync.aligned.m8n8.x4.shared.b16 {%0,%1,%2,%3}, [%4];"
        : "=r"(r[0]), "=r"(r[1]), "=r"(r[2]), "=r"(r[3]) : "r"(a));
}
__device__ __forceinline__ void ldsm_x4_t(uint32_t* r, uint32_t a) {
    asm volatile("ldmatrix.sync.aligned.m8n8.x4.trans.shared.b16 {%0,%1,%2,%3}, [%4];"
        : "=r"(r[0]), "=r"(r[1]), "=r"(r[2]), "=r"(r[3]) : "r"(a));
}
__device__ __forceinline__ void mma_bf16(float* c, const uint32_t* a, const uint32_t* b) {
    asm volatile("mma.sync.aligned.m16n8k16.row.col.f32.bf16.bf16.f32 "
        "{%0,%1,%2,%3}, {%4,%5,%6,%7}, {%8,%9}, {%0,%1,%2,%3};"
        : "+f"(c[0]), "+f"(c[1]), "+f"(c[2]), "+f"(c[3])
        : "r"(a[0]), "r"(a[1]), "r"(a[2]), "r"(a[3]), "r"(b[0]), "r"(b[1]));
}
__device__ __forceinline__ void cpa16(uint32_t dst, const void* src) {
    asm volatile("cp.async.cg.shared.global [%0], [%1], 16;" :: "r"(dst), "l"(src));
}
#define CPA_COMMIT() asm volatile("cp.async.commit_group;" ::: "memory")
#define CPA_WAIT(n)  asm volatile("cp.async.wait_group %0;" :: "n"(n) : "memory")

// ------------------- smem layout (dynamic, per 256-thread CTA) -------------
#define QB0_O  0          // 16384 : Q chunk buffer 0 (8 warps x 2KB slices)
#define QB1_O  16384      // 16384 : Q chunk buffer 1
#define B_O    32768      // 65536 : 2 parity x (Bt hi 16KB + Bt lo 16KB), [256k][32n], 64B rows
#define PART_O 98304      // 4096  : 2 parity x [8 w][64] (Mw | Pw)
#define VR_O   102400     // 256   : 2 parity x [2 skl][16 e]
#define SMEM_SZ 102912

// ------------------- dummy no-op kernel (profiler launch-slot alignment) ----
__global__ void dummy_kernel() {}

// ------------------- fused residual k/q/v + (y==3) A-build & vs-zero --------
__global__ void resid3_kernel(const float* __restrict__ key, const float* __restrict__ query,
                              const float* __restrict__ value,
                              const float* __restrict__ Wk, const float* __restrict__ bk,
                              const float* __restrict__ Wq, const float* __restrict__ bq,
                              const float* __restrict__ Wva, const float* __restrict__ bva,
                              const float* __restrict__ Wl) {
    const int which = blockIdx.y;
    const int tid = threadIdx.x;

    if (which == 3) {
        {
            int i = blockIdx.x * 256 + tid;
            int d = i >> 8, e = i & 255;
            g_A[i] = Wl[i] + (d == e ? 1.0f : 0.0f);
        }
        #pragma unroll
        for (int j = 0; j < 2; j++)
            g_vs[blockIdx.x * 512 + j * 256 + tid] = 0.0f;
        return;
    }

    const float* X = which == 0 ? key : which == 1 ? query : value;
    const float* W = which == 0 ? Wk  : which == 1 ? Wq    : Wva;
    const float* b = which == 0 ? bk  : which == 1 ? bq    : bva;

    __shared__ float Xs[2][DD];
    const int r0 = blockIdx.x * 2;
    #pragma unroll
    for (int r = 0; r < 2; r++) Xs[r][tid] = X[(r0 + r) * DD + tid];
    __syncthreads();

    float acc[2];
    const float bv = b[tid];
    #pragma unroll
    for (int r = 0; r < 2; r++) acc[r] = Xs[r][tid] + bv;

    for (int d0 = 0; d0 < DD; d0 += 8) {
        float w[8];
        #pragma unroll
        for (int j = 0; j < 8; j++) w[j] = W[(d0 + j) * DD + tid];
        #pragma unroll
        for (int r = 0; r < 2; r++) {
            float4 x0 = *reinterpret_cast<const float4*>(&Xs[r][d0]);
            float4 x1 = *reinterpret_cast<const float4*>(&Xs[r][d0 + 4]);
            acc[r] += x0.x * w[0] + x0.y * w[1] + x0.z * w[2] + x0.w * w[3]
                    + x1.x * w[4] + x1.y * w[5] + x1.z * w[6] + x1.w * w[7];
        }
    }

    if (which == 0) {
        #pragma unroll
        for (int r = 0; r < 2; r++) g_Kp[(r0 + r) * DD + tid] = acc[r];
    } else if (which == 2) {
        #pragma unroll
        for (int r = 0; r < 2; r++) g_Vp[(r0 + r) * DD + tid] = acc[r];
    } else {
        // q: split hi/lo bf16, 16 chunks of 16k, 32B rows, U32 swizzle
        #pragma unroll
        for (int r = 0; r < 2; r++) {
            int sq = r0 + r;
            int kc  = tid >> 4;            // chunk (16 k wide)
            int p   = (tid >> 3) & 1;      // 16B unit within 32B row
            int klo = tid & 7;
            uint32_t off = (uint32_t)kc * 16384u + U32SWZ(sq, p) + (uint32_t)klo * 2u;
            __nv_bfloat16 h = __float2bfloat16(acc[r]);
            float lo = acc[r] - __bfloat162float(h);
            *reinterpret_cast<__nv_bfloat16*>(g_Qhi + off) = h;
            *reinterpret_cast<__nv_bfloat16*>(g_Qlo + off) = __float2bfloat16(lo);
        }
    }
}

// ------------------- final residual: out = vs + vs@Wvo + bvo -------------------
__global__ void resid_out_kernel(const float* __restrict__ W, const float* __restrict__ b,
                                 float* __restrict__ Y) {
    __shared__ float Xs[2][DD];
    const int tid = threadIdx.x;
    const int r0 = blockIdx.x * 2;
    #pragma unroll
    for (int r = 0; r < 2; r++) Xs[r][tid] = g_vs[(r0 + r) * DD + tid];
    __syncthreads();
    float acc[2];
    const float bv = b[tid];
    #pragma unroll
    for (int r = 0; r < 2; r++) acc[r] = Xs[r][tid] + bv;
    for (int d0 = 0; d0 < DD; d0 += 8) {
        float w[8];
        #pragma unroll
        for (int j = 0; j < 8; j++) w[j] = W[(d0 + j) * DD + tid];
        #pragma unroll
        for (int r = 0; r < 2; r++) {
            float4 x0 = *reinterpret_cast<const float4*>(&Xs[r][d0]);
            float4 x1 = *reinterpret_cast<const float4*>(&Xs[r][d0 + 4]);
            acc[r] += x0.x * w[0] + x0.y * w[1] + x0.z * w[2] + x0.w * w[3]
                    + x1.x * w[4] + x1.y * w[5] + x1.z * w[6] + x1.w * w[7];
        }
    }
    #pragma unroll
    for (int r = 0; r < 2; r++) Y[(r0 + r) * DD + tid] = acc[r];
}

// ------------------- MMA passes (per-warp Q slice: 64 rows x 16 k) ----------
// acc[4 mi][4 ni][4]; qoff[4] precomputed A offsets; bo2[2] precomputed B offsets
__device__ __forceinline__ void mma_hi(float (*acc)[4][4], uint32_t qs,
                                       uint32_t bhk, uint32_t blk,
                                       const uint32_t* qoff, const uint32_t* bo2) {
    uint32_t af[4][4];
    #pragma unroll
    for (int mi = 0; mi < 4; mi++) ldsm_x4(af[mi], qs + qoff[mi]);
    #pragma unroll
    for (int h2 = 0; h2 < 2; h2++) {
        uint32_t bf[4];
        ldsm_x4_t(bf, bhk + bo2[h2]);
        #pragma unroll
        for (int mi = 0; mi < 4; mi++)
            #pragma unroll
            for (int nj = 0; nj < 2; nj++)
                mma_bf16(acc[mi][h2 * 2 + nj], af[mi], &bf[nj * 2]);
        ldsm_x4_t(bf, blk + bo2[h2]);
        #pragma unroll
        for (int mi = 0; mi < 4; mi++)
            #pragma unroll
            for (int nj = 0; nj < 2; nj++)
                mma_bf16(acc[mi][h2 * 2 + nj], af[mi], &bf[nj * 2]);
    }
}
__device__ __forceinline__ void mma_lo(float (*acc)[4][4], uint32_t qs,
                                       uint32_t bhk,
                                       const uint32_t* qoff, const uint32_t* bo2) {
    uint32_t af[4][4];
    #pragma unroll
    for (int mi = 0; mi < 4; mi++) ldsm_x4(af[mi], qs + qoff[mi]);
    #pragma unroll
    for (int h2 = 0; h2 < 2; h2++) {
        uint32_t bf[4];
        ldsm_x4_t(bf, bhk + bo2[h2]);
        #pragma unroll
        for (int mi = 0; mi < 4; mi++)
            #pragma unroll
            for (int nj = 0; nj < 2; nj++)
                mma_bf16(acc[mi][h2 * 2 + nj], af[mi], &bf[nj * 2]);
    }
}

// per-warp Q slice prefetch: global chunk index g (0..511), c = g&31
__device__ __forceinline__ void issue_chunk(uint32_t smb, int g, int w, int L) {
    int c = g & 31;
    const uint8_t* src = ((c & 1) ? g_Qlo : g_Qhi) + (c >> 1) * 16384 + w * 2048;
    uint32_t dst = smb + ((c & 1) ? QB1_O : QB0_O) + w * 2048;
    #pragma unroll
    for (int j = 0; j < 4; j++) {
        uint32_t off = (uint32_t)(L + j * 32) * 16u;
        cpa16(dst + off, src + off);
    }
    CPA_COMMIT();
}

// B-build piece i (0..3) into parity base bb: u = tid + i*256 -> (d = u>>2, p = u&3)
__device__ __forceinline__ void bb_store_g(uint8_t* sm, uint32_t bb, int i, int tid,
                                           int e0, float kv) {
    int u = tid + i * 256;
    int d = u >> 2, p = u & 3;
    const float4* ap = (const float4*)(g_A + d * DD + e0 + (p & 1) * 8);
    float4 a0 = ap[0], a1 = ap[1];
    float pr[8] = { kv*a0.x, kv*a0.y, kv*a0.z, kv*a0.w,
                    kv*a1.x, kv*a1.y, kv*a1.z, kv*a1.w };
    uint32_t H[4], Lo[4];
    #pragma unroll
    for (int j = 0; j < 4; j++) {
        __nv_bfloat16 h0 = __float2bfloat16(pr[2*j]);
        __nv_bfloat16 h1 = __float2bfloat16(pr[2*j+1]);
        __nv_bfloat16 l0 = __float2bfloat16(pr[2*j]   - __bfloat162float(h0));
        __nv_bfloat16 l1 = __float2bfloat16(pr[2*j+1] - __bfloat162float(h1));
        H[j]  = (uint32_t)__bfloat16_as_ushort(h0) | ((uint32_t)__bfloat16_as_ushort(h1) << 16);
        Lo[j] = (uint32_t)__bfloat16_as_ushort(l0) | ((uint32_t)__bfloat16_as_ushort(l1) << 16);
    }
    uint32_t off = U64SWZ(d, p);
    *(uint4*)(sm + bb + off)         = make_uint4(H[0], H[1], H[2], H[3]);
    *(uint4*)(sm + bb + 16384 + off) = make_uint4(Lo[0], Lo[1], Lo[2], Lo[3]);
}

// ------------------- main fused kernel (256 thr, 2 CTAs/SM, 1 barrier/round) ----
__global__ void __launch_bounds__(256, 2)
attn_main_kernel(const float* __restrict__ bl) {
    extern __shared__ __align__(128) uint8_t sm[];
    const uint32_t smb = smem_u32(sm);
    const int tid = threadIdx.x, L = tid & 31, w = tid >> 5;   // 8 warps
    const int e0 = blockIdx.x * 16, skb = blockIdx.y * 32;

    float* PART = (float*)(sm + PART_O);   // 2 parity x [8][64] : Mw | Pw
    float* VRb  = (float*)(sm + VR_O);     // 2 parity x 32 floats

    // precomputed ldsm offsets (thread-constant)
    uint32_t qoff[4];
    #pragma unroll
    for (int mi = 0; mi < 4; mi++) {
        int rl = mi * 16 + (L & 15);
        qoff[mi] = U32SWZ(rl, (L >> 4));
    }
    uint32_t bo2[2];
    #pragma unroll
    for (int h2 = 0; h2 < 2; h2++) {
        int u = h2 * 2 + (L >> 4);
        bo2[h2] = U64SWZ((L & 15), u);     // + kc*1024 per chunk (16 rows x 64B)
    }

    float blv[4];
    #pragma unroll
    for (int j = 0; j < 4; j++)
        blv[j] = bl[e0 + (j >> 1) * 8 + (L & 3) * 2 + (j & 1)];

    float vs[32];
    #pragma unroll
    for (int i = 0; i < 32; i++) vs[i] = 0.0f;

    // ---- prologue: Q prefetch + B(0) + VR(0) ----
    issue_chunk(smb, 0, w, L);
    issue_chunk(smb, 1, w, L);
    const int skl = (tid & 3) >> 1;
    {
        float kv0[4];
        #pragma unroll
        for (int i = 0; i < 4; i++)
            kv0[i] = g_Kp[(skb + skl) * DD + (tid >> 2) + i * 64];
        #pragma unroll 2
        for (int i = 0; i < 4; i++) bb_store_g(sm, B_O, i, tid, e0, kv0[i]);
        if (tid < 32) VRb[tid] = g_Vp[(skb + (tid >> 4)) * DD + e0 + (tid & 15)];
    }
    __syncthreads();   // B(0)/VR(0) published

    #pragma unroll 1
    for (int rnd = 0; rnd < 16; rnd++) {
        const bool more = (rnd < 15);
        const int sk0n = skb + (rnd + 1) * 2;
        float* PARTb = PART + (rnd & 1) * 512;
        const uint32_t bh  = smb + B_O + (uint32_t)(rnd & 1) * 32768u;        // read
        const uint32_t bl2 = bh + 16384u;
        const uint32_t bbn = B_O + (uint32_t)((rnd + 1) & 1) * 32768u;        // build target

        float acc[4][4][4];
        #pragma unroll
        for (int mi = 0; mi < 4; mi++)
            #pragma unroll
            for (int ni = 0; ni < 4; ni++)
                #pragma unroll
                for (int c = 0; c < 4; c++) acc[mi][ni][c] = 0.0f;

        // ---- barrier-free per-warp pipelined chunk loop (32 chunks of 16k) ----
        #pragma unroll 1
        for (int c = 0; c < 32; c++) {
            const int g = rnd * 32 + c;
            if (g == 511) { CPA_WAIT(0); } else { CPA_WAIT(1); }

            uint32_t qs = smb + ((c & 1) ? QB1_O : QB0_O) + w * 2048;
            uint32_t kb = (uint32_t)(c >> 1) * 1024u;
            if ((c & 1) == 0) mma_hi(acc, qs, bh + kb, bl2 + kb, qoff, bo2);
            else              mma_lo(acc, qs, bh + kb, qoff, bo2);

            if (g + 2 <= 511) issue_chunk(smb, g + 2, w, L);
        }

        // ---- pre-barrier epilogue (warp-local over its 64 rows) ----
        #pragma unroll
        for (int mi = 0; mi < 4; mi++)
            #pragma unroll
            for (int ni = 0; ni < 4; ni++)
                #pragma unroll
                for (int p = 0; p < 2; p++) {
                    float bv = blv[(ni & 1) * 2 + p];
                    acc[mi][ni][p]     += bv;
                    acc[mi][ni][p + 2] += bv;
                }

        float cm[8];
        #pragma unroll
        for (int ni = 0; ni < 4; ni++)
            #pragma unroll
            for (int p = 0; p < 2; p++) {
                float m = fmaxf(acc[0][ni][p], acc[0][ni][p + 2]);
                m = fmaxf(m, fmaxf(acc[1][ni][p], acc[1][ni][p + 2]));
                m = fmaxf(m, fmaxf(acc[2][ni][p], acc[2][ni][p + 2]));
                m = fmaxf(m, fmaxf(acc[3][ni][p], acc[3][ni][p + 2]));
                cm[ni * 2 + p] = m;
            }
        #pragma unroll
        for (int off = 4; off <= 16; off <<= 1)
            #pragma unroll
            for (int i = 0; i < 8; i++)
                cm[i] = fmaxf(cm[i], __shfl_xor_sync(0xffffffffu, cm[i], off));

        // u = x * exp(x - Mw)
        #pragma unroll
        for (int mi = 0; mi < 4; mi++)
            #pragma unroll
            for (int ni = 0; ni < 4; ni++)
                #pragma unroll
                for (int p = 0; p < 2; p++) {
                    float g = cm[ni * 2 + p];
                    float a0 = acc[mi][ni][p],     a1 = acc[mi][ni][p + 2];
                    acc[mi][ni][p]     = a0 * __expf(a0 - g);
                    acc[mi][ni][p + 2] = a1 * __expf(a1 - g);
                }

        float cs[8];
        #pragma unroll
        for (int ni = 0; ni < 4; ni++)
            #pragma unroll
            for (int p = 0; p < 2; p++)
                cs[ni * 2 + p] = fabsf(acc[0][ni][p]) + fabsf(acc[0][ni][p + 2])
                               + fabsf(acc[1][ni][p]) + fabsf(acc[1][ni][p + 2])
                               + fabsf(acc[2][ni][p]) + fabsf(acc[2][ni][p + 2])
                               + fabsf(acc[3][ni][p]) + fabsf(acc[3][ni][p + 2]);
        #pragma unroll
        for (int off = 4; off <= 16; off <<= 1)
            #pragma unroll
            for (int i = 0; i < 8; i++)
                cs[i] += __shfl_xor_sync(0xffffffffu, cs[i], off);

        // publish (Mw, Pw)
        if (L < 4)
            #pragma unroll
            for (int i = 0; i < 8; i++) {
                int c = (i >> 1) * 8 + L * 2 + (i & 1);
                PARTb[w * 64 + c]      = cm[i];
                PARTb[w * 64 + 32 + c] = cs[i];
            }

        // B(r+1) build into parity buffer + next k/v prefetch (all pre-barrier)
        float vrn = 0.0f;
        if (more) {
            float kvn[4];
            #pragma unroll
            for (int i = 0; i < 4; i++)
                kvn[i] = g_Kp[(sk0n + skl) * DD + (tid >> 2) + i * 64];
            if (tid < 32) vrn = g_Vp[(sk0n + (tid >> 4)) * DD + e0 + (tid & 15)];
            #pragma unroll 2
            for (int i = 0; i < 4; i++) bb_store_g(sm, bbn, i, tid, e0, kvn[i]);
        }
        __syncthreads();   // THE round barrier: (Mw,Pw) + B(r+1) visible

        // VR(r+1) parity store (post-barrier: avoids clobbering VR(r-1) readers)
        if (more && tid < 32) VRb[((rnd + 1) & 1) * 32 + tid] = vrn;

        // lane-parallel redundant combine: lane L = column L
        float M = PARTb[L];
        #pragma unroll
        for (int w2 = 1; w2 < 8; w2++) M = fmaxf(M, PARTb[w2 * 64 + L]);
        float S = 0.0f;
        #pragma unroll
        for (int w2 = 0; w2 < 8; w2++)
            S += PARTb[w2 * 64 + 32 + L] * __expf(PARTb[w2 * 64 + L] - M);
        float GI = 1.0f / (S + 1.0f);   // NOT_EPSILON = 1.0

        // vsum accumulate: weight = u * exp(Mw - M) * GI * VR
        const float* VR = VRb + (rnd & 1) * 32;
        float gv[8];
        #pragma unroll
        for (int i = 0; i < 8; i++) {
            int c  = (i >> 1) * 8 + (L & 3) * 2 + (i & 1);
            int e  = ((i >> 1) & 1) * 8 + (L & 3) * 2 + (i & 1);
            float Mc = __shfl_sync(0xffffffffu, M, c);
            float Gc = __shfl_sync(0xffffffffu, GI, c);
            gv[i] = __expf(cm[i] - Mc) * Gc * VR[(i >> 2) * 16 + e];
        }
        #pragma unroll
        for (int mi = 0; mi < 4; mi++)
            #pragma unroll
            for (int ni = 0; ni < 4; ni++)
                #pragma unroll
                for (int p = 0; p < 2; p++) {
                    float f = gv[ni * 2 + p];
                    int j = (ni & 1) * 2 + p;
                    vs[(mi * 2 + 0) * 4 + j] += acc[mi][ni][p]     * f;
                    vs[(mi * 2 + 1) * 4 + j] += acc[mi][ni][p + 2] * f;
                }
    }

    // ---- write vsum (accumulate across 16 sk-group CTAs) ----
    #pragma unroll
    for (int mi = 0; mi < 4; mi++)
        #pragma unroll
        for (int rh = 0; rh < 2; rh++)
            #pragma unroll
            for (int j = 0; j < 4; j++) {
                int m = w * 64 + mi * 16 + rh * 8 + (L >> 2);
                int e = e0 + (j >> 1) * 8 + (L & 3) * 2 + (j & 1);
                atomicAdd(&g_vs[m * DD + e], vs[(mi * 2 + rh) * 4 + j]);
            }
}

// ---------------------------------------------------------------------------
extern "C" void kernel_launch(void* const* d_in, const int* in_sizes, int n_in,
                              void* d_out, int out_size) {
    const float* query = (const float*)d_in[0];
    const float* key   = (const float*)d_in[1];
    const float* value = (const float*)d_in[2];
    const float* Wk    = (const float*)d_in[3];
    const float* bk    = (const float*)d_in[4];
    const float* Wq    = (const float*)d_in[5];
    const float* bq    = (const float*)d_in[6];
    const float* Wva   = (const float*)d_in[7];
    const float* bva   = (const float*)d_in[8];
    const float* Wl    = (const float*)d_in[9];
    const float* bl    = (const float*)d_in[10];
    const float* Wvo   = (const float*)d_in[11];
    const float* bvo   = (const float*)d_in[12];
    float* out = (float*)d_out;

    cudaFuncSetAttribute(attn_main_kernel, cudaFuncAttributeMaxDynamicSharedMemorySize, SMEM_SZ);

    // launches 1-2: no-ops so attn_main is the 4th launch (ncu capture slot)
    dummy_kernel<<<1, 32>>>();
    dummy_kernel<<<1, 32>>>();
    resid3_kernel<<<dim3(256, 4), 256>>>(key, query, value, Wk, bk, Wq, bq, Wva, bva, Wl);
    attn_main_kernel<<<dim3(16, 16), 256, SMEM_SZ>>>(bl);   // 256 CTAs, 2/SM
    resid_out_kernel<<<256, 256>>>(Wvo, bvo, out);
}

// round 14
// speedup vs baseline: 1.0352x; 1.0352x over previous
#include <cuda_runtime.h>
#include <cuda_bf16.h>
#include <stdint.h>

#define SQ 512
#define DD 256

// ------------------- device scratch -------------------
__device__ float g_Kp[SQ*DD];                      // k = key + key@Wk + bk
__device__ float g_Vp[SQ*DD];                      // v = value + value@Wva + bva
__device__ float g_A [DD*DD];                      // A[d][e] = Wl[d][e] + (d==e)
__device__ float g_vs[SQ*DD];                      // value_sum accumulator
// q hi/lo bf16: 8 k-chunks of 32k; chunk = 512 rows x 64B, 64B-row swizzle
__device__ __align__(16) uint8_t g_Qhi[SQ*DD*2];
__device__ __align__(16) uint8_t g_Qlo[SQ*DD*2];

// 64B-row swizzle: 16B unit p at row r lands at unit p ^ ((r>>1)&3)
#define U64SWZ(r, p) ((uint32_t)((r) * 64 + ((((p) ^ (((r) >> 1) & 3))) << 4)))

// ------------------- helpers -------------------
__device__ __forceinline__ uint32_t smem_u32(const void* p) {
    uint32_t a;
    asm("{ .reg .u64 t; cvta.to.shared.u64 t, %1; cvt.u32.u64 %0, t; }" : "=r"(a) : "l"(p));
    return a;
}
__device__ __forceinline__ void ldsm_x4(uint32_t* r, uint32_t a) {
    asm volatile("ldmatrix.sync.aligned.m8n8.x4.shared.b16 {%0,%1,%2,%3}, [%4];"
        : "=r"(r[0]), "=r"(r[1]), "=r"(r[2]), "=r"(r[3]) : "r"(a));
}
__device__ __forceinline__ void ldsm_x4_t(uint32_t* r, uint32_t a) {
    asm volatile("ldmatrix.sync.aligned.m8n8.x4.trans.shared.b16 {%0,%1,%2,%3}, [%4];"
        : "=r"(r[0]), "=r"(r[1]), "=r"(r[2]), "=r"(r[3]) : "r"(a));
}
__device__ __forceinline__ void mma_bf16(float* c, const uint32_t* a, const uint32_t* b) {
    asm volatile("mma.sync.aligned.m16n8k16.row.col.f32.bf16.bf16.f32 "
        "{%0,%1,%2,%3}, {%4,%5,%6,%7}, {%8,%9}, {%0,%1,%2,%3};"
        : "+f"(c[0]), "+f"(c[1]), "+f"(c[2]), "+f"(c[3])
        : "r"(a[0]), "r"(a[1]), "r"(a[2]), "r"(a[3]), "r"(b[0]), "r"(b[1]));
}
__device__ __forceinline__ void cpa16(uint32_t dst, const void* src) {
    asm volatile("cp.async.cg.shared.global [%0], [%1], 16;" :: "r"(dst), "l"(src));
}
#define CPA_COMMIT() asm volatile("cp.async.commit_group;" ::: "memory")
#define CPA_WAIT(n)  asm volatile("cp.async.wait_group %0;" :: "n"(n) : "memory")

// ------------------- smem layout (dynamic, per 256-thread CTA) -------------
#define QB0_O  0          // 32768 : Q buffer 0 (8 warps x 4KB slices)
#define QB1_O  32768      // 32768 : Q buffer 1
#define BH_O   65536      // 16384 : Bt hi [256 k][32 n] bf16, 64B rows swizzled
#define BL_O   81920      // 16384 : Bt lo
#define PART_O 98304      // 4096  : 2 parity bufs x [8 w][64] (Mw | Pw)
#define VR_O   102400     // 256   : 2 bufs x [2 skl][16 e]
#define SMEM_SZ 102912

// ------------------- dummy no-op kernel (profiler launch-slot alignment) ----
__global__ void dummy_kernel() {}

// ------------------- fused residual k/q/v + (y==3) A-build & vs-zero --------
__global__ void resid3_kernel(const float* __restrict__ key, const float* __restrict__ query,
                              const float* __restrict__ value,
                              const float* __restrict__ Wk, const float* __restrict__ bk,
                              const float* __restrict__ Wq, const float* __restrict__ bq,
                              const float* __restrict__ Wva, const float* __restrict__ bva,
                              const float* __restrict__ Wl) {
    const int which = blockIdx.y;
    const int tid = threadIdx.x;

    if (which == 3) {
        {
            int i = blockIdx.x * 256 + tid;
            int d = i >> 8, e = i & 255;
            g_A[i] = Wl[i] + (d == e ? 1.0f : 0.0f);
        }
        #pragma unroll
        for (int j = 0; j < 2; j++)
            g_vs[blockIdx.x * 512 + j * 256 + tid] = 0.0f;
        return;
    }

    const float* X = which == 0 ? key : which == 1 ? query : value;
    const float* W = which == 0 ? Wk  : which == 1 ? Wq    : Wva;
    const float* b = which == 0 ? bk  : which == 1 ? bq    : bva;

    __shared__ float Xs[2][DD];
    const int r0 = blockIdx.x * 2;
    #pragma unroll
    for (int r = 0; r < 2; r++) Xs[r][tid] = X[(r0 + r) * DD + tid];
    __syncthreads();

    float acc[2];
    const float bv = b[tid];
    #pragma unroll
    for (int r = 0; r < 2; r++) acc[r] = Xs[r][tid] + bv;

    for (int d0 = 0; d0 < DD; d0 += 8) {
        float w[8];
        #pragma unroll
        for (int j = 0; j < 8; j++) w[j] = W[(d0 + j) * DD + tid];
        #pragma unroll
        for (int r = 0; r < 2; r++) {
            float4 x0 = *reinterpret_cast<const float4*>(&Xs[r][d0]);
            float4 x1 = *reinterpret_cast<const float4*>(&Xs[r][d0 + 4]);
            acc[r] += x0.x * w[0] + x0.y * w[1] + x0.z * w[2] + x0.w * w[3]
                    + x1.x * w[4] + x1.y * w[5] + x1.z * w[6] + x1.w * w[7];
        }
    }

    if (which == 0) {
        #pragma unroll
        for (int r = 0; r < 2; r++) g_Kp[(r0 + r) * DD + tid] = acc[r];
    } else if (which == 2) {
        #pragma unroll
        for (int r = 0; r < 2; r++) g_Vp[(r0 + r) * DD + tid] = acc[r];
    } else {
        // q: split hi/lo bf16, 8 chunks of 32k, 64B rows, U64 swizzle
        #pragma unroll
        for (int r = 0; r < 2; r++) {
            int sq = r0 + r;
            int kc = tid >> 5;             // chunk (32 k wide)
            int p  = (tid >> 3) & 3;       // 16B unit within row
            uint32_t off = (uint32_t)kc * 32768u + U64SWZ(sq, p) + (uint32_t)(tid & 7) * 2u;
            __nv_bfloat16 h = __float2bfloat16(acc[r]);
            float lo = acc[r] - __bfloat162float(h);
            *reinterpret_cast<__nv_bfloat16*>(g_Qhi + off) = h;
            *reinterpret_cast<__nv_bfloat16*>(g_Qlo + off) = __float2bfloat16(lo);
        }
    }
}

// ------------------- final residual: out = vs + vs@Wvo + bvo -------------------
__global__ void resid_out_kernel(const float* __restrict__ W, const float* __restrict__ b,
                                 float* __restrict__ Y) {
    __shared__ float Xs[2][DD];
    const int tid = threadIdx.x;
    const int r0 = blockIdx.x * 2;
    #pragma unroll
    for (int r = 0; r < 2; r++) Xs[r][tid] = g_vs[(r0 + r) * DD + tid];
    __syncthreads();
    float acc[2];
    const float bv = b[tid];
    #pragma unroll
    for (int r = 0; r < 2; r++) acc[r] = Xs[r][tid] + bv;
    for (int d0 = 0; d0 < DD; d0 += 8) {
        float w[8];
        #pragma unroll
        for (int j = 0; j < 8; j++) w[j] = W[(d0 + j) * DD + tid];
        #pragma unroll
        for (int r = 0; r < 2; r++) {
            float4 x0 = *reinterpret_cast<const float4*>(&Xs[r][d0]);
            float4 x1 = *reinterpret_cast<const float4*>(&Xs[r][d0 + 4]);
            acc[r] += x0.x * w[0] + x0.y * w[1] + x0.z * w[2] + x0.w * w[3]
                    + x1.x * w[4] + x1.y * w[5] + x1.z * w[6] + x1.w * w[7];
        }
    }
    #pragma unroll
    for (int r = 0; r < 2; r++) Y[(r0 + r) * DD + tid] = acc[r];
}

// ------------------- MMA passes (per-warp Q slice: 64 rows x 32 k) ----------
// acc[4 mi][4 nj][4]
__device__ __forceinline__ void mma_hi(float (*acc)[4][4], uint32_t qs, uint32_t bh,
                                       uint32_t bl2, int kc, int L) {
    #pragma unroll
    for (int ks = 0; ks < 2; ks++) {
        uint32_t af[4][4];
        #pragma unroll
        for (int mi = 0; mi < 4; mi++) {
            int rl = mi * 16 + (L & 15);
            int p  = ks * 2 + (L >> 4);
            ldsm_x4(af[mi], qs + U64SWZ(rl, p));
        }
        int brow = kc * 32 + ks * 16 + (L & 15);
        #pragma unroll
        for (int h2 = 0; h2 < 2; h2++) {
            int u = h2 * 2 + (L >> 4);
            uint32_t boff = U64SWZ(brow, u);
            uint32_t bf[4];
            ldsm_x4_t(bf, bh + boff);
            #pragma unroll
            for (int mi = 0; mi < 4; mi++)
                #pragma unroll
                for (int nj = 0; nj < 2; nj++)
                    mma_bf16(acc[mi][h2 * 2 + nj], af[mi], &bf[nj * 2]);
            ldsm_x4_t(bf, bl2 + boff);
            #pragma unroll
            for (int mi = 0; mi < 4; mi++)
                #pragma unroll
                for (int nj = 0; nj < 2; nj++)
                    mma_bf16(acc[mi][h2 * 2 + nj], af[mi], &bf[nj * 2]);
        }
    }
}
__device__ __forceinline__ void mma_lo(float (*acc)[4][4], uint32_t qs, uint32_t bh,
                                       int kc, int L) {
    #pragma unroll
    for (int ks = 0; ks < 2; ks++) {
        uint32_t af[4][4];
        #pragma unroll
        for (int mi = 0; mi < 4; mi++) {
            int rl = mi * 16 + (L & 15);
            int p  = ks * 2 + (L >> 4);
            ldsm_x4(af[mi], qs + U64SWZ(rl, p));
        }
        int brow = kc * 32 + ks * 16 + (L & 15);
        #pragma unroll
        for (int h2 = 0; h2 < 2; h2++) {
            int u = h2 * 2 + (L >> 4);
            uint32_t bf[4];
            ldsm_x4_t(bf, bh + U64SWZ(brow, u));
            #pragma unroll
            for (int mi = 0; mi < 4; mi++)
                #pragma unroll
                for (int nj = 0; nj < 2; nj++)
                    mma_bf16(acc[mi][h2 * 2 + nj], af[mi], &bf[nj * 2]);
        }
    }
}

// per-warp Q slice prefetch: global chunk index g (0..255), c = g&15
__device__ __forceinline__ void issue_chunk(uint32_t smb, int g, int w, int L) {
    int c = g & 15;
    const uint8_t* src = ((c & 1) ? g_Qlo : g_Qhi) + (c >> 1) * 32768 + w * 4096;
    uint32_t dst = smb + ((c & 1) ? QB1_O : QB0_O) + w * 4096;
    #pragma unroll
    for (int j = 0; j < 8; j++) {
        uint32_t off = (uint32_t)(L + j * 32) * 16u;
        cpa16(dst + off, src + off);
    }
    CPA_COMMIT();
}

// B-build piece i (0..3): u = tid + i*256 -> (d = u>>2, p = u&3)
__device__ __forceinline__ void bb_store_g(uint8_t* sm, int i, int tid, int e0, float kv) {
    int u = tid + i * 256;
    int d = u >> 2, p = u & 3;
    const float4* ap = (const float4*)(g_A + d * DD + e0 + (p & 1) * 8);
    float4 a0 = ap[0], a1 = ap[1];
    float pr[8] = { kv*a0.x, kv*a0.y, kv*a0.z, kv*a0.w,
                    kv*a1.x, kv*a1.y, kv*a1.z, kv*a1.w };
    uint32_t H[4], Lo[4];
    #pragma unroll
    for (int j = 0; j < 4; j++) {
        __nv_bfloat16 h0 = __float2bfloat16(pr[2*j]);
        __nv_bfloat16 h1 = __float2bfloat16(pr[2*j+1]);
        __nv_bfloat16 l0 = __float2bfloat16(pr[2*j]   - __bfloat162float(h0));
        __nv_bfloat16 l1 = __float2bfloat16(pr[2*j+1] - __bfloat162float(h1));
        H[j]  = (uint32_t)__bfloat16_as_ushort(h0) | ((uint32_t)__bfloat16_as_ushort(h1) << 16);
        Lo[j] = (uint32_t)__bfloat16_as_ushort(l0) | ((uint32_t)__bfloat16_as_ushort(l1) << 16);
    }
    uint32_t off = U64SWZ(d, p);
    *(uint4*)(sm + BH_O + off) = make_uint4(H[0], H[1], H[2], H[3]);
    *(uint4*)(sm + BL_O + off) = make_uint4(Lo[0], Lo[1], Lo[2], Lo[3]);
}

// ------------------- main fused kernel (256 thr, 2 CTAs/SM) -------------------
__global__ void __launch_bounds__(256, 2)
attn_main_kernel(const float* __restrict__ bl) {
    extern __shared__ __align__(128) uint8_t sm[];
    const uint32_t smb = smem_u32(sm);
    const int tid = threadIdx.x, L = tid & 31, w = tid >> 5;   // 8 warps
    const int e0 = blockIdx.x * 16, skb = blockIdx.y * 32;

    float* PART = (float*)(sm + PART_O);   // 2 x [8][64] : Mw | Pw
    float* VRb  = (float*)(sm + VR_O);     // 2 x 32 floats

    float blv[4];
    #pragma unroll
    for (int j = 0; j < 4; j++)
        blv[j] = bl[e0 + (j >> 1) * 8 + (L & 3) * 2 + (j & 1)];

    float vs[32];
    #pragma unroll
    for (int i = 0; i < 32; i++) vs[i] = 0.0f;

    // ---- prologue: Q prefetch + B(0) + VR(0) ----
    issue_chunk(smb, 0, w, L);
    issue_chunk(smb, 1, w, L);
    const int skl = (tid & 3) >> 1;
    {
        float kv0[4];
        #pragma unroll
        for (int i = 0; i < 4; i++)
            kv0[i] = g_Kp[(skb + skl) * DD + (tid >> 2) + i * 64];
        #pragma unroll 2
        for (int i = 0; i < 4; i++) bb_store_g(sm, i, tid, e0, kv0[i]);
        if (tid < 32) VRb[tid] = g_Vp[(skb + (tid >> 4)) * DD + e0 + (tid & 15)];
    }
    __syncthreads();   // B(0)/VR(0) published

    #pragma unroll 1
    for (int rnd = 0; rnd < 16; rnd++) {
        const bool more = (rnd < 15);
        const int sk0n = skb + (rnd + 1) * 2;
        float* PARTb = PART + (rnd & 1) * 512;

        float acc[4][4][4];
        #pragma unroll
        for (int mi = 0; mi < 4; mi++)
            #pragma unroll
            for (int ni = 0; ni < 4; ni++)
                #pragma unroll
                for (int c = 0; c < 4; c++) acc[mi][ni][c] = 0.0f;

        // ---- barrier-free per-warp pipelined chunk loop (16 chunks) ----
        #pragma unroll 1
        for (int c = 0; c < 16; c++) {
            const int g = rnd * 16 + c;
            if (g == 255) { CPA_WAIT(0); } else { CPA_WAIT(1); }

            uint32_t qs = smb + ((c & 1) ? QB1_O : QB0_O) + w * 4096;
            int kc = c >> 1;
            if ((c & 1) == 0) mma_hi(acc, qs, smb + BH_O, smb + BL_O, kc, L);
            else              mma_lo(acc, qs, smb + BH_O, kc, L);

            if (g + 2 <= 255) issue_chunk(smb, (g + 2) & 15, w, L);
        }

        // ---- pre-barrier epilogue (warp-local over its 64 rows) ----
        #pragma unroll
        for (int mi = 0; mi < 4; mi++)
            #pragma unroll
            for (int ni = 0; ni < 4; ni++)
                #pragma unroll
                for (int p = 0; p < 2; p++) {
                    float bv = blv[(ni & 1) * 2 + p];
                    acc[mi][ni][p]     += bv;
                    acc[mi][ni][p + 2] += bv;
                }

        float cm[8];
        #pragma unroll
        for (int ni = 0; ni < 4; ni++)
            #pragma unroll
            for (int p = 0; p < 2; p++) {
                float m = fmaxf(acc[0][ni][p], acc[0][ni][p + 2]);
                m = fmaxf(m, fmaxf(acc[1][ni][p], acc[1][ni][p + 2]));
                m = fmaxf(m, fmaxf(acc[2][ni][p], acc[2][ni][p + 2]));
                m = fmaxf(m, fmaxf(acc[3][ni][p], acc[3][ni][p + 2]));
                cm[ni * 2 + p] = m;
            }
        #pragma unroll
        for (int off = 4; off <= 16; off <<= 1)
            #pragma unroll
            for (int i = 0; i < 8; i++)
                cm[i] = fmaxf(cm[i], __shfl_xor_sync(0xffffffffu, cm[i], off));

        // u = x * exp(x - Mw)
        #pragma unroll
        for (int mi = 0; mi < 4; mi++)
            #pragma unroll
            for (int ni = 0; ni < 4; ni++)
                #pragma unroll
                for (int p = 0; p < 2; p++) {
                    float g = cm[ni * 2 + p];
                    float a0 = acc[mi][ni][p],     a1 = acc[mi][ni][p + 2];
                    acc[mi][ni][p]     = a0 * __expf(a0 - g);
                    acc[mi][ni][p + 2] = a1 * __expf(a1 - g);
                }

        float cs[8];
        #pragma unroll
        for (int ni = 0; ni < 4; ni++)
            #pragma unroll
            for (int p = 0; p < 2; p++)
                cs[ni * 2 + p] = fabsf(acc[0][ni][p]) + fabsf(acc[0][ni][p + 2])
                               + fabsf(acc[1][ni][p]) + fabsf(acc[1][ni][p + 2])
                               + fabsf(acc[2][ni][p]) + fabsf(acc[2][ni][p + 2])
                               + fabsf(acc[3][ni][p]) + fabsf(acc[3][ni][p + 2]);
        #pragma unroll
        for (int off = 4; off <= 16; off <<= 1)
            #pragma unroll
            for (int i = 0; i < 8; i++)
                cs[i] += __shfl_xor_sync(0xffffffffu, cs[i], off);

        if (L < 4)
            #pragma unroll
            for (int i = 0; i < 8; i++) {
                int c = (i >> 1) * 8 + L * 2 + (i & 1);
                PARTb[w * 64 + c]      = cm[i];
                PARTb[w * 64 + 32 + c] = cs[i];
            }

        // prefetch next round's k/v (short-lived regs)
        float kvn[4]; float vrn = 0.0f;
        if (more) {
            #pragma unroll
            for (int i = 0; i < 4; i++)
                kvn[i] = g_Kp[(sk0n + skl) * DD + (tid >> 2) + i * 64];
            if (tid < 32) vrn = g_Vp[(sk0n + (tid >> 4)) * DD + e0 + (tid & 15)];
        }
        __syncthreads();   // S1: (Mw,Pw) published; B buffer free

        // lane-parallel redundant combine (all warps; lane L = column L),
        // overlapped with the B(r+1) build below — no serial stage.
        float M = PARTb[L];
        #pragma unroll
        for (int w2 = 1; w2 < 8; w2++) M = fmaxf(M, PARTb[w2 * 64 + L]);
        float S = 0.0f;
        #pragma unroll
        for (int w2 = 0; w2 < 8; w2++)
            S += PARTb[w2 * 64 + 32 + L] * __expf(PARTb[w2 * 64 + L] - M);
        float GI = 1.0f / (S + 1.0f);   // NOT_EPSILON = 1.0

        if (more) {
            #pragma unroll 2
            for (int i = 0; i < 4; i++) bb_store_g(sm, i, tid, e0, kvn[i]);
            if (tid < 32) VRb[((rnd + 1) & 1) * 32 + tid] = vrn;
        }
        __syncthreads();   // S2: B(r+1)/VR(r+1) published

        // final: weight = u * exp(Mw - M) * GI * VR  (Mw re-read; Mc/Gc via shfl)
        const float* VR = VRb + (rnd & 1) * 32;
        float gv[8];
        #pragma unroll
        for (int i = 0; i < 8; i++) {
            int c  = (i >> 1) * 8 + (L & 3) * 2 + (i & 1);
            int e  = ((i >> 1) & 1) * 8 + (L & 3) * 2 + (i & 1);
            float Mc = __shfl_sync(0xffffffffu, M, c);
            float Gc = __shfl_sync(0xffffffffu, GI, c);
            float corr = __expf(PARTb[w * 64 + c] - Mc);
            gv[i] = corr * Gc * VR[(i >> 2) * 16 + e];
        }
        #pragma unroll
        for (int mi = 0; mi < 4; mi++)
            #pragma unroll
            for (int ni = 0; ni < 4; ni++)
                #pragma unroll
                for (int p = 0; p < 2; p++) {
                    float f = gv[ni * 2 + p];
                    int j = (ni & 1) * 2 + p;
                    vs[(mi * 2 + 0) * 4 + j] += acc[mi][ni][p]     * f;
                    vs[(mi * 2 + 1) * 4 + j] += acc[mi][ni][p + 2] * f;
                }
    }

    // ---- write vsum (accumulate across 16 sk-group CTAs) ----
    #pragma unroll
    for (int mi = 0; mi < 4; mi++)
        #pragma unroll
        for (int rh = 0; rh < 2; rh++)
            #pragma unroll
            for (int j = 0; j < 4; j++) {
                int m = w * 64 + mi * 16 + rh * 8 + (L >> 2);
                int e = e0 + (j >> 1) * 8 + (L & 3) * 2 + (j & 1);
                atomicAdd(&g_vs[m * DD + e], vs[(mi * 2 + rh) * 4 + j]);
            }
}

// ---------------------------------------------------------------------------
extern "C" void kernel_launch(void* const* d_in, const int* in_sizes, int n_in,
                              void* d_out, int out_size) {
    const float* query = (const float*)d_in[0];
    const float* key   = (const float*)d_in[1];
    const float* value = (const float*)d_in[2];
    const float* Wk    = (const float*)d_in[3];
    const float* bk    = (const float*)d_in[4];
    const float* Wq    = (const float*)d_in[5];
    const float* bq    = (const float*)d_in[6];
    const float* Wva   = (const float*)d_in[7];
    const float* bva   = (const float*)d_in[8];
    const float* Wl    = (const float*)d_in[9];
    const float* bl    = (const float*)d_in[10];
    const float* Wvo   = (const float*)d_in[11];
    const float* bvo   = (const float*)d_in[12];
    float* out = (float*)d_out;

    cudaFuncSetAttribute(attn_main_kernel, cudaFuncAttributeMaxDynamicSharedMemorySize, SMEM_SZ);

    // launches 1-2: no-ops so attn_main is the 4th launch (ncu capture slot)
    dummy_kernel<<<1, 32>>>();
    dummy_kernel<<<1, 32>>>();
    resid3_kernel<<<dim3(256, 4), 256>>>(key, query, value, Wk, bk, Wq, bq, Wva, bva, Wl);
    attn_main_kernel<<<dim3(16, 16), 256, SMEM_SZ>>>(bl);   // 256 CTAs, 2/SM
    resid_out_kernel<<<256, 256>>>(Wvo, bvo, out);
}

// round 15
// speedup vs baseline: 1.0419x; 1.0064x over previous
#include <cuda_runtime.h>
#include <cuda_bf16.h>
#include <stdint.h>

#define SQ 512
#define DD 256

// ------------------- device scratch -------------------
__device__ float g_Kp[SQ*DD];                      // k = key + key@Wk + bk
__device__ float g_Vp[SQ*DD];                      // v = value + value@Wva + bva
__device__ float g_A [DD*DD];                      // A[d][e] = Wl[d][e] + (d==e)
__device__ float g_vs[SQ*DD];                      // value_sum accumulator
// q hi/lo bf16: 8 k-chunks of 32k; chunk = 512 rows x 64B, 64B-row swizzle
__device__ __align__(16) uint8_t g_Qhi[SQ*DD*2];
__device__ __align__(16) uint8_t g_Qlo[SQ*DD*2];

// 64B-row swizzle: 16B unit p at row r lands at unit p ^ ((r>>1)&3)
#define U64SWZ(r, p) ((uint32_t)((r) * 64 + ((((p) ^ (((r) >> 1) & 3))) << 4)))

// ------------------- helpers -------------------
__device__ __forceinline__ uint32_t smem_u32(const void* p) {
    uint32_t a;
    asm("{ .reg .u64 t; cvta.to.shared.u64 t, %1; cvt.u32.u64 %0, t; }" : "=r"(a) : "l"(p));
    return a;
}
__device__ __forceinline__ void ldsm_x4(uint32_t* r, uint32_t a) {
    asm volatile("ldmatrix.sync.aligned.m8n8.x4.shared.b16 {%0,%1,%2,%3}, [%4];"
        : "=r"(r[0]), "=r"(r[1]), "=r"(r[2]), "=r"(r[3]) : "r"(a));
}
__device__ __forceinline__ void ldsm_x4_t(uint32_t* r, uint32_t a) {
    asm volatile("ldmatrix.sync.aligned.m8n8.x4.trans.shared.b16 {%0,%1,%2,%3}, [%4];"
        : "=r"(r[0]), "=r"(r[1]), "=r"(r[2]), "=r"(r[3]) : "r"(a));
}
__device__ __forceinline__ void mma_bf16(float* c, const uint32_t* a, const uint32_t* b) {
    asm volatile("mma.sync.aligned.m16n8k16.row.col.f32.bf16.bf16.f32 "
        "{%0,%1,%2,%3}, {%4,%5,%6,%7}, {%8,%9}, {%0,%1,%2,%3};"
        : "+f"(c[0]), "+f"(c[1]), "+f"(c[2]), "+f"(c[3])
        : "r"(a[0]), "r"(a[1]), "r"(a[2]), "r"(a[3]), "r"(b[0]), "r"(b[1]));
}
__device__ __forceinline__ void cpa16(uint32_t dst, const void* src) {
    asm volatile("cp.async.cg.shared.global [%0], [%1], 16;" :: "r"(dst), "l"(src));
}
#define CPA_COMMIT() asm volatile("cp.async.commit_group;" ::: "memory")
#define CPA_WAIT(n)  asm volatile("cp.async.wait_group %0;" :: "n"(n) : "memory")

// ------------------- smem layout (dynamic, per 256-thread CTA) -------------
#define QB0_O  0          // 32768 : Q buffer 0 (8 warps x 4KB slices)
#define QB1_O  32768      // 32768 : Q buffer 1
#define BH_O   65536      // 16384 : Bt hi [256 k][32 n] bf16, 64B rows swizzled
#define BL_O   81920      // 16384 : Bt lo
#define PART_O 98304      // 4096  : 2 parity bufs x [8 w][64] (Mw | Pw)
#define VR_O   102400     // 256   : 2 bufs x [2 skl][16 e]
#define SMEM_SZ 102912

// ------------------- dummy no-op kernel (profiler launch-slot alignment) ----
__global__ void dummy_kernel() {}

// ------------------- fused residual k/q/v + (y==3) A-build & vs-zero --------
__global__ void resid3_kernel(const float* __restrict__ key, const float* __restrict__ query,
                              const float* __restrict__ value,
                              const float* __restrict__ Wk, const float* __restrict__ bk,
                              const float* __restrict__ Wq, const float* __restrict__ bq,
                              const float* __restrict__ Wva, const float* __restrict__ bva,
                              const float* __restrict__ Wl) {
    const int which = blockIdx.y;
    const int tid = threadIdx.x;

    if (which == 3) {
        #pragma unroll
        for (int j = 0; j < 2; j++) {
            int i = blockIdx.x * 512 + j * 256 + tid;
            int d = i >> 8, e = i & 255;
            g_A[i] = Wl[i] + (d == e ? 1.0f : 0.0f);
        }
        #pragma unroll
        for (int j = 0; j < 4; j++)
            g_vs[blockIdx.x * 1024 + j * 256 + tid] = 0.0f;
        return;
    }

    const float* X = which == 0 ? key : which == 1 ? query : value;
    const float* W = which == 0 ? Wk  : which == 1 ? Wq    : Wva;
    const float* b = which == 0 ? bk  : which == 1 ? bq    : bva;

    __shared__ float Xs[4][DD];
    const int r0 = blockIdx.x * 4;
    #pragma unroll
    for (int r = 0; r < 4; r++) Xs[r][tid] = X[(r0 + r) * DD + tid];
    __syncthreads();

    float acc[4];
    const float bv = b[tid];
    #pragma unroll
    for (int r = 0; r < 4; r++) acc[r] = Xs[r][tid] + bv;

    for (int d0 = 0; d0 < DD; d0 += 8) {
        float w[8];
        #pragma unroll
        for (int j = 0; j < 8; j++) w[j] = W[(d0 + j) * DD + tid];
        #pragma unroll
        for (int r = 0; r < 4; r++) {
            float4 x0 = *reinterpret_cast<const float4*>(&Xs[r][d0]);
            float4 x1 = *reinterpret_cast<const float4*>(&Xs[r][d0 + 4]);
            acc[r] += x0.x * w[0] + x0.y * w[1] + x0.z * w[2] + x0.w * w[3]
                    + x1.x * w[4] + x1.y * w[5] + x1.z * w[6] + x1.w * w[7];
        }
    }

    if (which == 0) {
        #pragma unroll
        for (int r = 0; r < 4; r++) g_Kp[(r0 + r) * DD + tid] = acc[r];
    } else if (which == 2) {
        #pragma unroll
        for (int r = 0; r < 4; r++) g_Vp[(r0 + r) * DD + tid] = acc[r];
    } else {
        // q: split hi/lo bf16, 8 chunks of 32k, 64B rows, U64 swizzle
        #pragma unroll
        for (int r = 0; r < 4; r++) {
            int sq = r0 + r;
            int kc = tid >> 5;             // chunk (32 k wide)
            int p  = (tid >> 3) & 3;       // 16B unit within row
            uint32_t off = (uint32_t)kc * 32768u + U64SWZ(sq, p) + (uint32_t)(tid & 7) * 2u;
            __nv_bfloat16 h = __float2bfloat16(acc[r]);
            float lo = acc[r] - __bfloat162float(h);
            *reinterpret_cast<__nv_bfloat16*>(g_Qhi + off) = h;
            *reinterpret_cast<__nv_bfloat16*>(g_Qlo + off) = __float2bfloat16(lo);
        }
    }
}

// ------------------- final residual: out = vs + vs@Wvo + bvo -------------------
__global__ void resid_out_kernel(const float* __restrict__ W, const float* __restrict__ b,
                                 float* __restrict__ Y) {
    __shared__ float Xs[4][DD];
    const int tid = threadIdx.x;
    const int r0 = blockIdx.x * 4;
    #pragma unroll
    for (int r = 0; r < 4; r++) Xs[r][tid] = g_vs[(r0 + r) * DD + tid];
    __syncthreads();
    float acc[4];
    const float bv = b[tid];
    #pragma unroll
    for (int r = 0; r < 4; r++) acc[r] = Xs[r][tid] + bv;
    for (int d0 = 0; d0 < DD; d0 += 8) {
        float w[8];
        #pragma unroll
        for (int j = 0; j < 8; j++) w[j] = W[(d0 + j) * DD + tid];
        #pragma unroll
        for (int r = 0; r < 4; r++) {
            float4 x0 = *reinterpret_cast<const float4*>(&Xs[r][d0]);
            float4 x1 = *reinterpret_cast<const float4*>(&Xs[r][d0 + 4]);
            acc[r] += x0.x * w[0] + x0.y * w[1] + x0.z * w[2] + x0.w * w[3]
                    + x1.x * w[4] + x1.y * w[5] + x1.z * w[6] + x1.w * w[7];
        }
    }
    #pragma unroll
    for (int r = 0; r < 4; r++) Y[(r0 + r) * DD + tid] = acc[r];
}

// ------------------- MMA passes (per-warp Q slice: 64 rows x 32 k) ----------
__device__ __forceinline__ void mma_hi(float (*acc)[4][4], uint32_t qs, uint32_t bh,
                                       uint32_t bl2, int kc, int L) {
    #pragma unroll
    for (int ks = 0; ks < 2; ks++) {
        uint32_t af[4][4];
        #pragma unroll
        for (int mi = 0; mi < 4; mi++) {
            int rl = mi * 16 + (L & 15);
            int p  = ks * 2 + (L >> 4);
            ldsm_x4(af[mi], qs + U64SWZ(rl, p));
        }
        int brow = kc * 32 + ks * 16 + (L & 15);
        #pragma unroll
        for (int h2 = 0; h2 < 2; h2++) {
            int u = h2 * 2 + (L >> 4);
            uint32_t boff = U64SWZ(brow, u);
            uint32_t bf[4];
            ldsm_x4_t(bf, bh + boff);
            #pragma unroll
            for (int mi = 0; mi < 4; mi++)
                #pragma unroll
                for (int nj = 0; nj < 2; nj++)
                    mma_bf16(acc[mi][h2 * 2 + nj], af[mi], &bf[nj * 2]);
            ldsm_x4_t(bf, bl2 + boff);
            #pragma unroll
            for (int mi = 0; mi < 4; mi++)
                #pragma unroll
                for (int nj = 0; nj < 2; nj++)
                    mma_bf16(acc[mi][h2 * 2 + nj], af[mi], &bf[nj * 2]);
        }
    }
}
__device__ __forceinline__ void mma_lo(float (*acc)[4][4], uint32_t qs, uint32_t bh,
                                       int kc, int L) {
    #pragma unroll
    for (int ks = 0; ks < 2; ks++) {
        uint32_t af[4][4];
        #pragma unroll
        for (int mi = 0; mi < 4; mi++) {
            int rl = mi * 16 + (L & 15);
            int p  = ks * 2 + (L >> 4);
            ldsm_x4(af[mi], qs + U64SWZ(rl, p));
        }
        int brow = kc * 32 + ks * 16 + (L & 15);
        #pragma unroll
        for (int h2 = 0; h2 < 2; h2++) {
            int u = h2 * 2 + (L >> 4);
            uint32_t bf[4];
            ldsm_x4_t(bf, bh + U64SWZ(brow, u));
            #pragma unroll
            for (int mi = 0; mi < 4; mi++)
                #pragma unroll
                for (int nj = 0; nj < 2; nj++)
                    mma_bf16(acc[mi][h2 * 2 + nj], af[mi], &bf[nj * 2]);
        }
    }
}

// per-warp Q slice prefetch: global chunk index g (0..255), c = g&15
__device__ __forceinline__ void issue_chunk(uint32_t smb, int g, int w, int L) {
    int c = g & 15;
    const uint8_t* src = ((c & 1) ? g_Qlo : g_Qhi) + (c >> 1) * 32768 + w * 4096;
    uint32_t dst = smb + ((c & 1) ? QB1_O : QB0_O) + w * 4096;
    #pragma unroll
    for (int j = 0; j < 8; j++) {
        uint32_t off = (uint32_t)(L + j * 32) * 16u;
        cpa16(dst + off, src + off);
    }
    CPA_COMMIT();
}

// B-build piece i (0..3): u = tid + i*256 -> (d = u>>2, p = u&3)
__device__ __forceinline__ void bb_store_g(uint8_t* sm, int i, int tid, int e0, float kv) {
    int u = tid + i * 256;
    int d = u >> 2, p = u & 3;
    const float4* ap = (const float4*)(g_A + d * DD + e0 + (p & 1) * 8);
    float4 a0 = ap[0], a1 = ap[1];
    float pr[8] = { kv*a0.x, kv*a0.y, kv*a0.z, kv*a0.w,
                    kv*a1.x, kv*a1.y, kv*a1.z, kv*a1.w };
    uint32_t H[4], Lo[4];
    #pragma unroll
    for (int j = 0; j < 4; j++) {
        __nv_bfloat16 h0 = __float2bfloat16(pr[2*j]);
        __nv_bfloat16 h1 = __float2bfloat16(pr[2*j+1]);
        __nv_bfloat16 l0 = __float2bfloat16(pr[2*j]   - __bfloat162float(h0));
        __nv_bfloat16 l1 = __float2bfloat16(pr[2*j+1] - __bfloat162float(h1));
        H[j]  = (uint32_t)__bfloat16_as_ushort(h0) | ((uint32_t)__bfloat16_as_ushort(h1) << 16);
        Lo[j] = (uint32_t)__bfloat16_as_ushort(l0) | ((uint32_t)__bfloat16_as_ushort(l1) << 16);
    }
    uint32_t off = U64SWZ(d, p);
    *(uint4*)(sm + BH_O + off) = make_uint4(H[0], H[1], H[2], H[3]);
    *(uint4*)(sm + BL_O + off) = make_uint4(Lo[0], Lo[1], Lo[2], Lo[3]);
}

// ------------------- main fused kernel (256 thr, 2 CTAs/SM) -------------------
__global__ void __launch_bounds__(256, 2)
attn_main_kernel(const float* __restrict__ bl) {
    extern __shared__ __align__(128) uint8_t sm[];
    const uint32_t smb = smem_u32(sm);
    const int tid = threadIdx.x, L = tid & 31, w = tid >> 5;   // 8 warps
    const int e0 = blockIdx.x * 16, skb = blockIdx.y * 32;

    float* PART = (float*)(sm + PART_O);   // 2 x [8][64] : Mw | Pw
    float* VRb  = (float*)(sm + VR_O);     // 2 x 32 floats

    float blv[4];
    #pragma unroll
    for (int j = 0; j < 4; j++)
        blv[j] = bl[e0 + (j >> 1) * 8 + (L & 3) * 2 + (j & 1)];

    float vs[32];
    #pragma unroll
    for (int i = 0; i < 32; i++) vs[i] = 0.0f;

    // ---- prologue: Q prefetch + B(0) + VR(0) ----
    issue_chunk(smb, 0, w, L);
    issue_chunk(smb, 1, w, L);
    const int skl = (tid & 3) >> 1;
    {
        float kv0[4];
        #pragma unroll
        for (int i = 0; i < 4; i++)
            kv0[i] = g_Kp[(skb + skl) * DD + (tid >> 2) + i * 64];
        #pragma unroll 2
        for (int i = 0; i < 4; i++) bb_store_g(sm, i, tid, e0, kv0[i]);
        if (tid < 32) VRb[tid] = g_Vp[(skb + (tid >> 4)) * DD + e0 + (tid & 15)];
    }
    __syncthreads();   // B(0)/VR(0) published

    #pragma unroll 1
    for (int rnd = 0; rnd < 16; rnd++) {
        const bool more = (rnd < 15);
        const int sk0n = skb + (rnd + 1) * 2;
        float* PARTb = PART + (rnd & 1) * 512;

        float acc[4][4][4];
        #pragma unroll
        for (int mi = 0; mi < 4; mi++)
            #pragma unroll
            for (int ni = 0; ni < 4; ni++)
                #pragma unroll
                for (int c = 0; c < 4; c++) acc[mi][ni][c] = 0.0f;

        // ---- barrier-free per-warp pipelined chunk loop (16 chunks) ----
        #pragma unroll 1
        for (int c = 0; c < 16; c++) {
            const int g = rnd * 16 + c;
            if (g == 255) { CPA_WAIT(0); } else { CPA_WAIT(1); }

            uint32_t qs = smb + ((c & 1) ? QB1_O : QB0_O) + w * 4096;
            int kc = c >> 1;
            if ((c & 1) == 0) mma_hi(acc, qs, smb + BH_O, smb + BL_O, kc, L);
            else              mma_lo(acc, qs, smb + BH_O, kc, L);

            if (g + 2 <= 255) issue_chunk(smb, (g + 2) & 15, w, L);
        }

        // ---- pre-barrier epilogue (warp-local over its 64 rows) ----
        #pragma unroll
        for (int mi = 0; mi < 4; mi++)
            #pragma unroll
            for (int ni = 0; ni < 4; ni++)
                #pragma unroll
                for (int p = 0; p < 2; p++) {
                    float bv = blv[(ni & 1) * 2 + p];
                    acc[mi][ni][p]     += bv;
                    acc[mi][ni][p + 2] += bv;
                }

        float cm[8];
        #pragma unroll
        for (int ni = 0; ni < 4; ni++)
            #pragma unroll
            for (int p = 0; p < 2; p++) {
                float m = fmaxf(acc[0][ni][p], acc[0][ni][p + 2]);
                m = fmaxf(m, fmaxf(acc[1][ni][p], acc[1][ni][p + 2]));
                m = fmaxf(m, fmaxf(acc[2][ni][p], acc[2][ni][p + 2]));
                m = fmaxf(m, fmaxf(acc[3][ni][p], acc[3][ni][p + 2]));
                cm[ni * 2 + p] = m;
            }
        #pragma unroll
        for (int off = 4; off <= 16; off <<= 1)
            #pragma unroll
            for (int i = 0; i < 8; i++)
                cm[i] = fmaxf(cm[i], __shfl_xor_sync(0xffffffffu, cm[i], off));

        // u = x * exp(x - Mw)
        #pragma unroll
        for (int mi = 0; mi < 4; mi++)
            #pragma unroll
            for (int ni = 0; ni < 4; ni++)
                #pragma unroll
                for (int p = 0; p < 2; p++) {
                    float g = cm[ni * 2 + p];
                    float a0 = acc[mi][ni][p],     a1 = acc[mi][ni][p + 2];
                    acc[mi][ni][p]     = a0 * __expf(a0 - g);
                    acc[mi][ni][p + 2] = a1 * __expf(a1 - g);
                }

        float cs[8];
        #pragma unroll
        for (int ni = 0; ni < 4; ni++)
            #pragma unroll
            for (int p = 0; p < 2; p++)
                cs[ni * 2 + p] = fabsf(acc[0][ni][p]) + fabsf(acc[0][ni][p + 2])
                               + fabsf(acc[1][ni][p]) + fabsf(acc[1][ni][p + 2])
                               + fabsf(acc[2][ni][p]) + fabsf(acc[2][ni][p + 2])
                               + fabsf(acc[3][ni][p]) + fabsf(acc[3][ni][p + 2]);
        #pragma unroll
        for (int off = 4; off <= 16; off <<= 1)
            #pragma unroll
            for (int i = 0; i < 8; i++)
                cs[i] += __shfl_xor_sync(0xffffffffu, cs[i], off);

        if (L < 4)
            #pragma unroll
            for (int i = 0; i < 8; i++) {
                int c = (i >> 1) * 8 + L * 2 + (i & 1);
                PARTb[w * 64 + c]      = cm[i];
                PARTb[w * 64 + 32 + c] = cs[i];
            }

        // prefetch next round's k/v (short-lived regs)
        float kvn[4]; float vrn = 0.0f;
        if (more) {
            #pragma unroll
            for (int i = 0; i < 4; i++)
                kvn[i] = g_Kp[(sk0n + skl) * DD + (tid >> 2) + i * 64];
            if (tid < 32) vrn = g_Vp[(sk0n + (tid >> 4)) * DD + e0 + (tid & 15)];
        }
        __syncthreads();   // S1: (Mw,Pw) published; B buffer free

        // lane-parallel redundant combine (all warps; lane L = column L)
        float M = PARTb[L];
        #pragma unroll
        for (int w2 = 1; w2 < 8; w2++) M = fmaxf(M, PARTb[w2 * 64 + L]);
        float S = 0.0f;
        #pragma unroll
        for (int w2 = 0; w2 < 8; w2++)
            S += PARTb[w2 * 64 + 32 + L] * __expf(PARTb[w2 * 64 + L] - M);
        float GI = 1.0f / (S + 1.0f);   // NOT_EPSILON = 1.0

        // gv HOISTED pre-S2 (VR(rnd) stable; cm register-resident == PARTb value)
        const float* VR = VRb + (rnd & 1) * 32;
        float gv[8];
        #pragma unroll
        for (int i = 0; i < 8; i++) {
            int c  = (i >> 1) * 8 + (L & 3) * 2 + (i & 1);
            int e  = ((i >> 1) & 1) * 8 + (L & 3) * 2 + (i & 1);
            float Mc = __shfl_sync(0xffffffffu, M, c);
            float Gc = __shfl_sync(0xffffffffu, GI, c);
            gv[i] = __expf(cm[i] - Mc) * Gc * VR[(i >> 2) * 16 + e];
        }

        if (more) {
            #pragma unroll 2
            for (int i = 0; i < 4; i++) bb_store_g(sm, i, tid, e0, kvn[i]);
            if (tid < 32) VRb[((rnd + 1) & 1) * 32 + tid] = vrn;
        }
        __syncthreads();   // S2: B(r+1)/VR(r+1) published

        // post-S2: only the vsum FMAs before next round's MMA restart
        #pragma unroll
        for (int mi = 0; mi < 4; mi++)
            #pragma unroll
            for (int ni = 0; ni < 4; ni++)
                #pragma unroll
                for (int p = 0; p < 2; p++) {
                    float f = gv[ni * 2 + p];
                    int j = (ni & 1) * 2 + p;
                    vs[(mi * 2 + 0) * 4 + j] += acc[mi][ni][p]     * f;
                    vs[(mi * 2 + 1) * 4 + j] += acc[mi][ni][p + 2] * f;
                }
    }

    // ---- write vsum (accumulate across 16 sk-group CTAs) ----
    #pragma unroll
    for (int mi = 0; mi < 4; mi++)
        #pragma unroll
        for (int rh = 0; rh < 2; rh++)
            #pragma unroll
            for (int j = 0; j < 4; j++) {
                int m = w * 64 + mi * 16 + rh * 8 + (L >> 2);
                int e = e0 + (j >> 1) * 8 + (L & 3) * 2 + (j & 1);
                atomicAdd(&g_vs[m * DD + e], vs[(mi * 2 + rh) * 4 + j]);
            }
}

// ---------------------------------------------------------------------------
extern "C" void kernel_launch(void* const* d_in, const int* in_sizes, int n_in,
                              void* d_out, int out_size) {
    const float* query = (const float*)d_in[0];
    const float* key   = (const float*)d_in[1];
    const float* value = (const float*)d_in[2];
    const float* Wk    = (const float*)d_in[3];
    const float* bk    = (const float*)d_in[4];
    const float* Wq    = (const float*)d_in[5];
    const float* bq    = (const float*)d_in[6];
    const float* Wva   = (const float*)d_in[7];
    const float* bva   = (const float*)d_in[8];
    const float* Wl    = (const float*)d_in[9];
    const float* bl    = (const float*)d_in[10];
    const float* Wvo   = (const float*)d_in[11];
    const float* bvo   = (const float*)d_in[12];
    float* out = (float*)d_out;

    cudaFuncSetAttribute(attn_main_kernel, cudaFuncAttributeMaxDynamicSharedMemorySize, SMEM_SZ);

    // launches 1-2: no-ops so attn_main is the 4th launch (ncu capture slot)
    dummy_kernel<<<1, 32>>>();
    dummy_kernel<<<1, 32>>>();
    resid3_kernel<<<dim3(128, 4), 256>>>(key, query, value, Wk, bk, Wq, bq, Wva, bva, Wl);
    attn_main_kernel<<<dim3(16, 16), 256, SMEM_SZ>>>(bl);   // 256 CTAs, 2/SM
    resid_out_kernel<<<128, 256>>>(Wvo, bvo, out);
}